// round 6
// baseline (speedup 1.0000x reference)
#include <cuda_runtime.h>
#include <cstdint>

// ---------------------------------------------------------------------------
// C3 layer: x(128,6,256,256) -> out(128,16,252,252), 5x5 VALID convs.
// Direct conv: 2 horizontal pixels x all 16 output channels per thread,
// FFMA2 (fma.rn.f32x2) accumulators. Input row loaded as 3x float2 so the
// natural register pairs ARE the even-shift operand pairs (P0,P2,P4); only
// the two overlapping pairs (P1,P3) need a pack. 16 acc pairs -> low
// pairing pressure -> no MOV storm (the R2/R3 failure mode).
// Weights in smem as duplicated (w,w) pairs, rows padded to 48B.
// ---------------------------------------------------------------------------

__device__ constexpr int POC[6][10] = {
    {0, 4, 5, 6,  9, 10, 11, 12, 14, 15},
    {0, 1, 5, 6,  7, 10, 11, 12, 13, 15},
    {0, 1, 2, 6,  7,  8, 11, 13, 14, 15},
    {1, 2, 3, 6,  7,  8,  9, 12, 14, 15},
    {2, 3, 4, 7,  8,  9, 10, 12, 13, 15},
    {3, 4, 5, 8,  9, 10, 11, 13, 14, 15}
};
__device__ constexpr int POFF[6][10] = {
    {  0, 300, 375, 450, 750,  850,  950, 1050, 1250, 1350},
    { 25,  75, 400, 475, 550,  875,  975, 1075, 1150, 1375},
    { 50, 100, 150, 500, 575,  650, 1000, 1175, 1275, 1400},
    {125, 175, 225, 525, 600,  675,  775, 1100, 1300, 1425},
    {200, 250, 325, 625, 700,  800,  900, 1125, 1200, 1450},
    {275, 350, 425, 725, 825,  925, 1025, 1225, 1325, 1475}
};

#define FMA2(acc, a, b) asm("fma.rn.f32x2 %0, %1, %2, %0;" : "+l"(acc) : "l"(a), "l"(b))

__device__ __forceinline__ unsigned long long pack2(float lo, float hi) {
    unsigned long long r;
    asm("mov.b64 %0, {%1, %2};" : "=l"(r) : "f"(lo), "f"(hi));
    return r;
}

union F2 {
    float2 f;
    unsigned long long u;
};
union F4 {
    float4 f;
    unsigned long long u[2];
};

__global__ __launch_bounds__(256, 3)
void c3_kernel(const float* __restrict__ x,
               const float* __restrict__ w3, const float* __restrict__ b3,
               const float* __restrict__ w4, const float* __restrict__ b4,
               const float* __restrict__ w6, const float* __restrict__ b6,
               float* __restrict__ out)
{
    // Dup-packed weights: [c][j][ky] rows of 5 (w,w) pairs padded to 12
    // floats (48B): LDS.128 + LDS.128 + LDS.64 at immediate offsets.
    __shared__ __align__(16) float wsm[6 * 10 * 5 * 12];
    __shared__ float bsm[16];

    const int tid = threadIdx.y * 128 + threadIdx.x;

    for (int idx = tid; idx < 1500; idx += 256) {
        int kx = idx % 5;
        int t  = idx / 5;
        int ky = t % 5;  t /= 5;
        int j  = t % 10;
        int c  = t / 10;
        int off = POFF[c][j] + ky * 5 + kx;
        float w = (off < 450) ? w3[off]
                : (off < 1350) ? w4[off - 450]
                               : w6[off - 1350];
        int d = ((c * 10 + j) * 5 + ky) * 12 + kx * 2;
        wsm[d]     = w;
        wsm[d + 1] = w;
    }
    if (tid < 16) {
        bsm[tid] = (tid < 6) ? b3[tid] : (tid < 15) ? b4[tid - 6] : b6[0];
    }
    __syncthreads();

    const int b   = blockIdx.z;
    const int p   = blockIdx.y * 2 + threadIdx.y;   // output row, 0..251
    const int q0r = threadIdx.x * 2;                // 0..254
    const int q0  = (q0r > 250) ? 250 : q0r;        // tx 126/127 duplicate 250

    // 16 oc x 2 px accumulators, one f32x2 pair each.
    unsigned long long acc[16];
    #pragma unroll
    for (int oc = 0; oc < 16; ++oc) {
        acc[oc] = pack2(bsm[oc], bsm[oc]);
    }

    #pragma unroll
    for (int c = 0; c < 6; ++c) {
        const float* xp = x + (((size_t)b * 6 + c) * 256 + p) * 256 + q0;
        #pragma unroll
        for (int ky = 0; ky < 5; ++ky) {
            // 6 input values as 3x float2 (8B aligned): natural pairs.
            F2 A, B, C;
            A.f = *(const float2*)(xp + ky * 256);      // (v0,v1)
            B.f = *(const float2*)(xp + ky * 256 + 2);  // (v2,v3)
            C.f = *(const float2*)(xp + ky * 256 + 4);  // (v4,v5)

            unsigned long long P0 = A.u;                 // shift 0
            unsigned long long P1 = pack2(A.f.y, B.f.x); // shift 1
            unsigned long long P2 = B.u;                 // shift 2
            unsigned long long P3 = pack2(B.f.y, C.f.x); // shift 3
            unsigned long long P4 = C.u;                 // shift 4

            #pragma unroll
            for (int j = 0; j < 10; ++j) {
                const int oc   = POC[c][j];
                const int base = ((c * 10 + j) * 5 + ky) * 12;
                F4 wA; wA.f = *(const float4*)&wsm[base];      // W0, W1
                F4 wB; wB.f = *(const float4*)&wsm[base + 4];  // W2, W3
                F2 wC; wC.f = *(const float2*)&wsm[base + 8];  // W4

                FMA2(acc[oc], wA.u[0], P0);
                FMA2(acc[oc], wA.u[1], P1);
                FMA2(acc[oc], wB.u[0], P2);
                FMA2(acc[oc], wB.u[1], P3);
                FMA2(acc[oc], wC.u,    P4);
            }
        }
    }

    #pragma unroll
    for (int oc = 0; oc < 16; ++oc) {
        F2 r;
        r.u = acc[oc];
        *(float2*)(out + (((size_t)b * 16 + oc) * 252 + p) * 252 + q0) = r.f;
    }
}

extern "C" void kernel_launch(void* const* d_in, const int* in_sizes, int n_in,
                              void* d_out, int out_size)
{
    const float* x  = (const float*)d_in[0];
    const float* w3 = (const float*)d_in[1];
    const float* b3 = (const float*)d_in[2];
    const float* w4 = (const float*)d_in[3];
    const float* b4 = (const float*)d_in[4];
    const float* w6 = (const float*)d_in[5];
    const float* b6 = (const float*)d_in[6];
    float* out = (float*)d_out;

    dim3 block(128, 2, 1);       // 128 col-pairs x 2 rows
    dim3 grid(1, 126, 128);      // 126*2 = 252 rows, 128 batch
    c3_kernel<<<grid, block>>>(x, w3, b3, w4, b4, w6, b6, out);
}

// round 7
// speedup vs baseline: 1.3638x; 1.3638x over previous
#include <cuda_runtime.h>
#include <cstdint>

// ---------------------------------------------------------------------------
// C3 layer: x(128,6,256,256) -> out(128,16,252,252), 5x5 VALID convs.
// Direct conv: 2 horizontal pixels x all 16 output channels per thread,
// pure scalar fp32 FFMA. Small register footprint (32 acc regs) so
// __launch_bounds__(256,4) gives 4 CTAs/SM = 32 warps (occ ~50%) on the
// 64K-reg/SM file -> issue-port utilization is the binder, not latency.
// Weights in smem, 5-float rows padded to 8 (32B): LDS.128+LDS.32 at
// immediate offsets.
// ---------------------------------------------------------------------------

__device__ constexpr int POC[6][10] = {
    {0, 4, 5, 6,  9, 10, 11, 12, 14, 15},
    {0, 1, 5, 6,  7, 10, 11, 12, 13, 15},
    {0, 1, 2, 6,  7,  8, 11, 13, 14, 15},
    {1, 2, 3, 6,  7,  8,  9, 12, 14, 15},
    {2, 3, 4, 7,  8,  9, 10, 12, 13, 15},
    {3, 4, 5, 8,  9, 10, 11, 13, 14, 15}
};
__device__ constexpr int POFF[6][10] = {
    {  0, 300, 375, 450, 750,  850,  950, 1050, 1250, 1350},
    { 25,  75, 400, 475, 550,  875,  975, 1075, 1150, 1375},
    { 50, 100, 150, 500, 575,  650, 1000, 1175, 1275, 1400},
    {125, 175, 225, 525, 600,  675,  775, 1100, 1300, 1425},
    {200, 250, 325, 625, 700,  800,  900, 1125, 1200, 1450},
    {275, 350, 425, 725, 825,  925, 1025, 1225, 1325, 1475}
};

__global__ __launch_bounds__(256, 4)
void c3_kernel(const float* __restrict__ x,
               const float* __restrict__ w3, const float* __restrict__ b3,
               const float* __restrict__ w4, const float* __restrict__ b4,
               const float* __restrict__ w6, const float* __restrict__ b6,
               float* __restrict__ out)
{
    // Weight rows [c][j][ky][0..4], padded to 8 floats (32B).
    __shared__ __align__(16) float wsm[6 * 10 * 5 * 8];
    __shared__ float bsm[16];

    const int tid = threadIdx.y * 128 + threadIdx.x;

    for (int idx = tid; idx < 1500; idx += 256) {
        int kx = idx % 5;
        int t  = idx / 5;
        int ky = t % 5;  t /= 5;
        int j  = t % 10;
        int c  = t / 10;
        int off = POFF[c][j] + ky * 5 + kx;
        float w = (off < 450) ? w3[off]
                : (off < 1350) ? w4[off - 450]
                               : w6[off - 1350];
        wsm[(((c * 10 + j) * 5 + ky) * 8) + kx] = w;
    }
    if (tid < 16) {
        bsm[tid] = (tid < 6) ? b3[tid] : (tid < 15) ? b4[tid - 6] : b6[0];
    }
    __syncthreads();

    const int b   = blockIdx.z;
    const int p   = blockIdx.y * 2 + threadIdx.y;   // output row, 0..251
    const int q0r = threadIdx.x * 2;                // 0..254
    const int q0  = (q0r > 250) ? 250 : q0r;        // tx 126/127 duplicate 250

    // 16 oc x 2 px accumulators.
    float acc0[16], acc1[16];
    #pragma unroll
    for (int oc = 0; oc < 16; ++oc) {
        float bv = bsm[oc];
        acc0[oc] = bv;
        acc1[oc] = bv;
    }

    #pragma unroll
    for (int c = 0; c < 6; ++c) {
        const float* xp = x + (((size_t)b * 6 + c) * 256 + p) * 256 + q0;
        #pragma unroll
        for (int ky = 0; ky < 5; ++ky) {
            // 6 input values as 3x float2 (8B aligned).
            float2 A = *(const float2*)(xp + ky * 256);
            float2 B = *(const float2*)(xp + ky * 256 + 2);
            float2 C = *(const float2*)(xp + ky * 256 + 4);
            float v0 = A.x, v1 = A.y, v2 = B.x, v3 = B.y, v4 = C.x, v5 = C.y;

            #pragma unroll
            for (int j = 0; j < 10; ++j) {
                const int oc   = POC[c][j];
                const int base = ((c * 10 + j) * 5 + ky) * 8;
                float4 wv = *(const float4*)&wsm[base];
                float  w4v = wsm[base + 4];

                float s0 = acc0[oc];
                float s1 = acc1[oc];
                s0 = wv.x * v0 + s0;   s1 = wv.x * v1 + s1;
                s0 = wv.y * v1 + s0;   s1 = wv.y * v2 + s1;
                s0 = wv.z * v2 + s0;   s1 = wv.z * v3 + s1;
                s0 = wv.w * v3 + s0;   s1 = wv.w * v4 + s1;
                s0 = w4v  * v4 + s0;   s1 = w4v  * v5 + s1;
                acc0[oc] = s0;
                acc1[oc] = s1;
            }
        }
    }

    #pragma unroll
    for (int oc = 0; oc < 16; ++oc) {
        float2 r;
        r.x = acc0[oc];
        r.y = acc1[oc];
        *(float2*)(out + (((size_t)b * 16 + oc) * 252 + p) * 252 + q0) = r;
    }
}

extern "C" void kernel_launch(void* const* d_in, const int* in_sizes, int n_in,
                              void* d_out, int out_size)
{
    const float* x  = (const float*)d_in[0];
    const float* w3 = (const float*)d_in[1];
    const float* b3 = (const float*)d_in[2];
    const float* w4 = (const float*)d_in[3];
    const float* b4 = (const float*)d_in[4];
    const float* w6 = (const float*)d_in[5];
    const float* b6 = (const float*)d_in[6];
    float* out = (float*)d_out;

    dim3 block(128, 2, 1);       // 128 col-pairs x 2 rows
    dim3 grid(1, 126, 128);      // 126*2 = 252 rows, 128 batch
    c3_kernel<<<grid, block>>>(x, w3, b3, w4, b4, w6, b6, out);
}